// round 3
// baseline (speedup 1.0000x reference)
#include <cuda_runtime.h>

// ---------------------------------------------------------------------------
// DynEdge: 4x DynamicEdgeConv (kNN in feature space, K=8) + MLP head.
// Strategy: factorized edge linear1 (c_i + b_j), fp32 tiled SGEMMs.
// ---------------------------------------------------------------------------

#define GB    64
#define GN    512
#define NODES 32768          // GB*GN
#define KNB   8

static inline int cdiv(int a, int b) { return (a + b - 1) / b; }

__device__ __forceinline__ float lrelu(float v) { return v >= 0.0f ? v : 0.01f * v; }

// ------------------------------- scratch -----------------------------------
__device__ float g_x0p  [NODES * 8];                 // x padded [32768,8]
__device__ float g_featv[4 * NODES * 256];           // x1..x4
__device__ float g_gramv[(size_t)GB * GN * GN];      // per-graph Gram
__device__ float g_x2v  [NODES];
__device__ int   g_knnv [NODES * KNB];               // global neighbor ids
__device__ float g_wcombv[256 * 768];                // [(Wa-Wb) | Wb | 0] padded
__device__ float g_cbv  [(size_t)NODES * 768];       // [c | b] per node
__device__ float g_H1v  [(size_t)NODES * KNB * 336]; // edge hidden
__device__ float g_Ev   [(size_t)NODES * KNB * 256]; // edge out (also reused for m1 h)
__device__ float g_hcatv[(size_t)NODES * 1032];
__device__ float g_hmv  [(size_t)NODES * 384];
__device__ float g_w1padv[1032 * 384];
__device__ float g_b1padv[384];
__device__ float g_w2padv[384 * 256];
__device__ float g_poolv[GB * 256];

// ------------------------------ SGEMM (NN) ---------------------------------
// C[M,N] = A[M,K] @ B[K,N]. Requires M%128==0, N%128==0, K%8==0, 16B-aligned
// rows. 128x128 block tile, 8x8 per-thread microtile, double-buffered smem.
// EPI==1: C = lrelu(C + bias[col]).
template <int EPI>
__global__ __launch_bounds__(256)
void sgemm_nn(const float* __restrict__ A, const float* __restrict__ B,
              const float* __restrict__ bias, float* __restrict__ C,
              int M, int N, int K)
{
    __shared__ float As[2][8][128];
    __shared__ float Bs[2][8][128];
    const int tid  = threadIdx.x;
    const int m0   = blockIdx.x * 128;
    const int n0   = blockIdx.y * 128;
    const int tx   = tid & 15;
    const int ty   = tid >> 4;
    const int arow = tid >> 1;
    const int acol = (tid & 1) << 2;
    const int brow = tid >> 5;
    const int bcol = (tid & 31) << 2;

    const float* Ap = A + (size_t)(m0 + arow) * K + acol;
    const float* Bp = B + (size_t)brow * N + (n0 + bcol);

    float4 av = *(const float4*)Ap;
    float4 bv = *(const float4*)Bp;
    As[0][acol + 0][arow] = av.x;
    As[0][acol + 1][arow] = av.y;
    As[0][acol + 2][arow] = av.z;
    As[0][acol + 3][arow] = av.w;
    *(float4*)&Bs[0][brow][bcol] = bv;
    __syncthreads();

    float acc[8][8];
#pragma unroll
    for (int i = 0; i < 8; i++)
#pragma unroll
        for (int j = 0; j < 8; j++) acc[i][j] = 0.0f;

    const int nk = K >> 3;
    for (int kc = 0; kc < nk; kc++) {
        const int cur = kc & 1;
        const bool has_next = (kc + 1 < nk);
        if (has_next) {
            av = *(const float4*)(Ap + (kc + 1) * 8);
            bv = *(const float4*)(Bp + (size_t)(kc + 1) * 8 * N);
        }
#pragma unroll
        for (int k = 0; k < 8; k++) {
            float ar[8], br[8];
            *(float4*)&ar[0] = *(const float4*)&As[cur][k][ty * 4];
            *(float4*)&ar[4] = *(const float4*)&As[cur][k][64 + ty * 4];
            *(float4*)&br[0] = *(const float4*)&Bs[cur][k][tx * 4];
            *(float4*)&br[4] = *(const float4*)&Bs[cur][k][64 + tx * 4];
#pragma unroll
            for (int i = 0; i < 8; i++)
#pragma unroll
                for (int j = 0; j < 8; j++)
                    acc[i][j] = fmaf(ar[i], br[j], acc[i][j]);
        }
        if (has_next) {
            const int nxt = cur ^ 1;
            As[nxt][acol + 0][arow] = av.x;
            As[nxt][acol + 1][arow] = av.y;
            As[nxt][acol + 2][arow] = av.z;
            As[nxt][acol + 3][arow] = av.w;
            *(float4*)&Bs[nxt][brow][bcol] = bv;
        }
        __syncthreads();
    }

#pragma unroll
    for (int i = 0; i < 8; i++) {
        const int r = m0 + ((i < 4) ? (ty * 4 + i) : (64 + ty * 4 + i - 4));
#pragma unroll
        for (int h = 0; h < 2; h++) {
            const int c = n0 + h * 64 + tx * 4;
            float4 v;
            v.x = acc[i][h * 4 + 0];
            v.y = acc[i][h * 4 + 1];
            v.z = acc[i][h * 4 + 2];
            v.w = acc[i][h * 4 + 3];
            if (EPI == 1) {
                v.x = lrelu(v.x + bias[c + 0]);
                v.y = lrelu(v.y + bias[c + 1]);
                v.z = lrelu(v.z + bias[c + 2]);
                v.w = lrelu(v.w + bias[c + 3]);
            }
            *(float4*)&C[(size_t)r * N + c] = v;
        }
    }
}

// ----------------------- batched Gram: G = X @ X^T -------------------------
// grid (4, 4, 64): 128x128 tile of one graph's 512x512 Gram. ldx = K (8 or 256).
__global__ __launch_bounds__(256)
void gram_nt(const float* __restrict__ X, int ldx, int K, float* __restrict__ G)
{
    const int b = blockIdx.z;
    const float* A = X + (size_t)b * GN * ldx;
    float* C = G + (size_t)b * GN * GN;
    __shared__ float As[2][8][128];
    __shared__ float Bs[2][8][128];
    const int tid  = threadIdx.x;
    const int m0   = blockIdx.x * 128;
    const int n0   = blockIdx.y * 128;
    const int tx   = tid & 15;
    const int ty   = tid >> 4;
    const int arow = tid >> 1;
    const int acol = (tid & 1) << 2;

    const float* Ap = A + (size_t)(m0 + arow) * ldx + acol;
    const float* Bp = A + (size_t)(n0 + arow) * ldx + acol;

    float4 av = *(const float4*)Ap;
    float4 bv = *(const float4*)Bp;
    As[0][acol + 0][arow] = av.x; As[0][acol + 1][arow] = av.y;
    As[0][acol + 2][arow] = av.z; As[0][acol + 3][arow] = av.w;
    Bs[0][acol + 0][arow] = bv.x; Bs[0][acol + 1][arow] = bv.y;
    Bs[0][acol + 2][arow] = bv.z; Bs[0][acol + 3][arow] = bv.w;
    __syncthreads();

    float acc[8][8];
#pragma unroll
    for (int i = 0; i < 8; i++)
#pragma unroll
        for (int j = 0; j < 8; j++) acc[i][j] = 0.0f;

    const int nk = K >> 3;
    for (int kc = 0; kc < nk; kc++) {
        const int cur = kc & 1;
        const bool has_next = (kc + 1 < nk);
        if (has_next) {
            av = *(const float4*)(Ap + (kc + 1) * 8);
            bv = *(const float4*)(Bp + (kc + 1) * 8);
        }
#pragma unroll
        for (int k = 0; k < 8; k++) {
            float ar[8], br[8];
            *(float4*)&ar[0] = *(const float4*)&As[cur][k][ty * 4];
            *(float4*)&ar[4] = *(const float4*)&As[cur][k][64 + ty * 4];
            *(float4*)&br[0] = *(const float4*)&Bs[cur][k][tx * 4];
            *(float4*)&br[4] = *(const float4*)&Bs[cur][k][64 + tx * 4];
#pragma unroll
            for (int i = 0; i < 8; i++)
#pragma unroll
                for (int j = 0; j < 8; j++)
                    acc[i][j] = fmaf(ar[i], br[j], acc[i][j]);
        }
        if (has_next) {
            const int nxt = cur ^ 1;
            As[nxt][acol + 0][arow] = av.x; As[nxt][acol + 1][arow] = av.y;
            As[nxt][acol + 2][arow] = av.z; As[nxt][acol + 3][arow] = av.w;
            Bs[nxt][acol + 0][arow] = bv.x; Bs[nxt][acol + 1][arow] = bv.y;
            Bs[nxt][acol + 2][arow] = bv.z; Bs[nxt][acol + 3][arow] = bv.w;
        }
        __syncthreads();
    }

#pragma unroll
    for (int i = 0; i < 8; i++) {
        const int r = m0 + ((i < 4) ? (ty * 4 + i) : (64 + ty * 4 + i - 4));
#pragma unroll
        for (int h = 0; h < 2; h++) {
            const int c = n0 + h * 64 + tx * 4;
            float4 v;
            v.x = acc[i][h * 4 + 0];
            v.y = acc[i][h * 4 + 1];
            v.z = acc[i][h * 4 + 2];
            v.w = acc[i][h * 4 + 3];
            *(float4*)&C[(size_t)r * GN + c] = v;
        }
    }
}

// ------------------------------- helpers -----------------------------------
__global__ void x2_kernel(const float* __restrict__ X, int Fp, float* __restrict__ x2)
{
    int i = blockIdx.x * blockDim.x + threadIdx.x;
    if (i >= NODES) return;
    const float* p = X + (size_t)i * Fp;
    float s = 0.f;
    for (int f = 0; f < Fp; f += 4) {
        float4 v = *(const float4*)(p + f);
        s += v.x * v.x + v.y * v.y + v.z * v.z + v.w * v.w;
    }
    x2[i] = s;
}

// top-8 smallest distances, stable on ties (lower index wins) to match lax.top_k
__global__ __launch_bounds__(512)
void knn_kernel(const float* __restrict__ G, const float* __restrict__ x2,
                int* __restrict__ knn)
{
    const int b = blockIdx.x;
    const int i = threadIdx.x;
    __shared__ float sx2[GN];
    sx2[i] = x2[b * GN + i];
    __syncthreads();
    const float x2i = sx2[i];
    const float4* row = (const float4*)(G + ((size_t)b * GN + i) * GN);

    float bd[8]; int bi[8];
#pragma unroll
    for (int k = 0; k < 8; k++) { bd[k] = 3.4e38f; bi[k] = 0; }

    for (int q = 0; q < GN / 4; q++) {
        float4 g4 = row[q];
        const int j = q * 4;
        float dv0 = x2i + sx2[j + 0] - 2.0f * g4.x;
        float dv1 = x2i + sx2[j + 1] - 2.0f * g4.y;
        float dv2 = x2i + sx2[j + 2] - 2.0f * g4.z;
        float dv3 = x2i + sx2[j + 3] - 2.0f * g4.w;
        float dv[4] = {dv0, dv1, dv2, dv3};
#pragma unroll
        for (int u = 0; u < 4; u++) {
            float d = dv[u];
            if (d < bd[7]) {
                bd[7] = d; bi[7] = j + u;
#pragma unroll
                for (int s = 7; s > 0; s--) {
                    if (bd[s] < bd[s - 1]) {
                        float td = bd[s]; bd[s] = bd[s - 1]; bd[s - 1] = td;
                        int   ti = bi[s]; bi[s] = bi[s - 1]; bi[s - 1] = ti;
                    } else break;
                }
            }
        }
    }
#pragma unroll
    for (int k = 0; k < 8; k++)
        knn[((size_t)b * GN + i) * KNB + k] = b * GN + bi[k];
}

// wcomb[f, 0:336]   = W1[f] - W1[F+f]   (multiplies x_i)
// wcomb[f, 336:672] = W1[F+f]           (multiplies x_j)
// wcomb[f, 672:768] = 0 ; rows f>=F zero.
__global__ void build_wcomb(const float* __restrict__ W1, int F, int Fp,
                            float* __restrict__ out)
{
    int idx = blockIdx.x * blockDim.x + threadIdx.x;
    if (idx >= Fp * 768) return;
    int f = idx / 768, t = idx % 768;
    float v = 0.f;
    if (f < F) {
        if (t < 336)      v = W1[f * 336 + t] - W1[(F + f) * 336 + t];
        else if (t < 672) v = W1[(F + f) * 336 + (t - 336)];
    }
    out[idx] = v;
}

__global__ void pad_w(const float* __restrict__ src, int R, int Cs,
                      float* __restrict__ dst, int Rp, int Cp)
{
    int idx = blockIdx.x * blockDim.x + threadIdx.x;
    if (idx >= Rp * Cp) return;
    int r = idx / Cp, c = idx % Cp;
    dst[idx] = (r < R && c < Cs) ? src[r * Cs + c] : 0.f;
}

// H1[edge, t] = lrelu(c_i[t] + b_j[t] + bias1[t])
__global__ void edge_build(const float* __restrict__ cb, const int* __restrict__ knn,
                           const float* __restrict__ b1, float* __restrict__ H1)
{
    const int node = blockIdx.x;
    const int tid = threadIdx.x;
    __shared__ int js[KNB];
    if (tid < KNB) js[tid] = knn[(size_t)node * KNB + tid];
    __syncthreads();
    const float* ci = cb + (size_t)node * 768;
#pragma unroll
    for (int k = 0; k < KNB; k++) {
        const float* bj = cb + (size_t)js[k] * 768 + 336;
        float* out = H1 + ((size_t)node * KNB + k) * 336;
        for (int t = tid; t < 336; t += blockDim.x)
            out[t] = lrelu(ci[t] + bj[t] + b1[t]);
    }
}

// out[node,c] = lrelu(max_k E[node*8+k, c] + b2[c])   (lrelu monotone)
__global__ void edge_reduce(const float* __restrict__ E, const float* __restrict__ b2,
                            float* __restrict__ out)
{
    const int node = blockIdx.x;
    const int c = threadIdx.x;
    float m = -3.4e38f;
#pragma unroll
    for (int k = 0; k < KNB; k++)
        m = fmaxf(m, E[((size_t)node * KNB + k) * 256 + c]);
    out[(size_t)node * 256 + c] = lrelu(m + b2[c]);
}

__global__ void concat_kernel(const float* __restrict__ x0,
                              const float* __restrict__ f1, const float* __restrict__ f2,
                              const float* __restrict__ f3, const float* __restrict__ f4,
                              float* __restrict__ out)
{
    const int row = blockIdx.x;
    for (int col = threadIdx.x; col < 1032; col += blockDim.x) {
        float v;
        if (col < 6)         v = x0[row * 6 + col];
        else if (col < 262)  v = f1[(size_t)row * 256 + col - 6];
        else if (col < 518)  v = f2[(size_t)row * 256 + col - 262];
        else if (col < 774)  v = f3[(size_t)row * 256 + col - 518];
        else if (col < 1030) v = f4[(size_t)row * 256 + col - 774];
        else                 v = 0.f;
        out[(size_t)row * 1032 + col] = v;
    }
}

__global__ void pool_kernel(const float* __restrict__ h, float* __restrict__ g)
{
    const int b = blockIdx.x, c = threadIdx.x;
    float s = 0.f;
    for (int n = 0; n < GN; n++)
        s += h[((size_t)b * GN + n) * 256 + c];
    g[b * 256 + c] = s * (1.0f / GN);
}

__global__ void head_kernel(const float* __restrict__ gpool,
                            const float* __restrict__ w1, const float* __restrict__ b1,
                            const float* __restrict__ w2, const float* __restrict__ b2,
                            float* __restrict__ out)
{
    const int b = blockIdx.x, tid = threadIdx.x;  // 128 threads
    __shared__ float g[256];
    __shared__ float mid[128];
    g[tid] = gpool[b * 256 + tid];
    g[tid + 128] = gpool[b * 256 + tid + 128];
    __syncthreads();
    float s = b1[tid];
    for (int f = 0; f < 256; f++)
        s = fmaf(g[f], w1[f * 128 + tid], s);
    mid[tid] = lrelu(s);
    __syncthreads();
    if (tid < 3) {
        float s2 = b2[tid];
        for (int f = 0; f < 128; f++)
            s2 = fmaf(mid[f], w2[f * 3 + tid], s2);
        out[b * 3 + tid] = s2;
    }
}

// ------------------------------- launcher ----------------------------------
extern "C" void kernel_launch(void* const* d_in, const int* in_sizes, int n_in,
                              void* d_out, int out_size)
{
    (void)in_sizes; (void)n_in; (void)out_size;
    const float* x = (const float*)d_in[0];
    const float* cw1[4] = {(const float*)d_in[3],  (const float*)d_in[7],
                           (const float*)d_in[11], (const float*)d_in[15]};
    const float* cb1[4] = {(const float*)d_in[4],  (const float*)d_in[8],
                           (const float*)d_in[12], (const float*)d_in[16]};
    const float* cw2[4] = {(const float*)d_in[5],  (const float*)d_in[9],
                           (const float*)d_in[13], (const float*)d_in[17]};
    const float* cb2[4] = {(const float*)d_in[6],  (const float*)d_in[10],
                           (const float*)d_in[14], (const float*)d_in[18]};
    const float* m1w1 = (const float*)d_in[19];
    const float* m1b1 = (const float*)d_in[20];
    const float* m1w2 = (const float*)d_in[21];
    const float* m1b2 = (const float*)d_in[22];
    const float* m2w1 = (const float*)d_in[23];
    const float* m2b1 = (const float*)d_in[24];
    const float* m2w2 = (const float*)d_in[25];
    const float* m2b2 = (const float*)d_in[26];

    float *p_x0p, *p_feat, *p_gram, *p_x2, *p_wcomb, *p_cb, *p_H1, *p_E;
    float *p_hcat, *p_hm, *p_w1pad, *p_b1pad, *p_w2pad, *p_pool;
    int* p_knn;
    cudaGetSymbolAddress((void**)&p_x0p,   g_x0p);
    cudaGetSymbolAddress((void**)&p_feat,  g_featv);
    cudaGetSymbolAddress((void**)&p_gram,  g_gramv);
    cudaGetSymbolAddress((void**)&p_x2,    g_x2v);
    cudaGetSymbolAddress((void**)&p_knn,   g_knnv);
    cudaGetSymbolAddress((void**)&p_wcomb, g_wcombv);
    cudaGetSymbolAddress((void**)&p_cb,    g_cbv);
    cudaGetSymbolAddress((void**)&p_H1,    g_H1v);
    cudaGetSymbolAddress((void**)&p_E,     g_Ev);
    cudaGetSymbolAddress((void**)&p_hcat,  g_hcatv);
    cudaGetSymbolAddress((void**)&p_hm,    g_hmv);
    cudaGetSymbolAddress((void**)&p_w1pad, g_w1padv);
    cudaGetSymbolAddress((void**)&p_b1pad, g_b1padv);
    cudaGetSymbolAddress((void**)&p_w2pad, g_w2padv);
    cudaGetSymbolAddress((void**)&p_pool,  g_poolv);

    // ---- prep: pad inputs/weights for the GEMM tiling constraints ----
    pad_w<<<cdiv(NODES * 8, 256), 256>>>(x, NODES, 6, p_x0p, NODES, 8);
    pad_w<<<cdiv(1032 * 384, 256), 256>>>(m1w1, 1030, 336, p_w1pad, 1032, 384);
    pad_w<<<cdiv(384, 256), 256>>>(m1b1, 1, 336, p_b1pad, 1, 384);
    pad_w<<<cdiv(384 * 256, 256), 256>>>(m1w2, 336, 256, p_w2pad, 384, 256);

    // ---- 4 DynamicEdgeConv layers ----
    for (int l = 0; l < 4; l++) {
        const float* in = (l == 0) ? p_x0p : (p_feat + (size_t)(l - 1) * NODES * 256);
        const int Fp = (l == 0) ? 8 : 256;
        const int F  = (l == 0) ? 6 : 256;

        x2_kernel<<<cdiv(NODES, 256), 256>>>(in, Fp, p_x2);
        gram_nt<<<dim3(4, 4, GB), 256>>>(in, Fp, Fp, p_gram);
        knn_kernel<<<GB, GN>>>(p_gram, p_x2, p_knn);

        build_wcomb<<<cdiv(Fp * 768, 256), 256>>>(cw1[l], F, Fp, p_wcomb);
        sgemm_nn<0><<<dim3(NODES / 128, 6), 256>>>(in, p_wcomb, nullptr, p_cb,
                                                   NODES, 768, Fp);
        edge_build<<<NODES, 256>>>(p_cb, p_knn, cb1[l], p_H1);
        sgemm_nn<0><<<dim3(NODES * KNB / 128, 2), 256>>>(p_H1, cw2[l], nullptr, p_E,
                                                         NODES * KNB, 256, 336);
        edge_reduce<<<NODES, 256>>>(p_E, cb2[l], p_feat + (size_t)l * NODES * 256);
    }

    // ---- head ----
    concat_kernel<<<NODES, 256>>>(x,
                                  p_feat + (size_t)0 * NODES * 256,
                                  p_feat + (size_t)1 * NODES * 256,
                                  p_feat + (size_t)2 * NODES * 256,
                                  p_feat + (size_t)3 * NODES * 256,
                                  p_hcat);
    sgemm_nn<1><<<dim3(NODES / 128, 3), 256>>>(p_hcat, p_w1pad, p_b1pad, p_hm,
                                               NODES, 384, 1032);
    sgemm_nn<1><<<dim3(NODES / 128, 2), 256>>>(p_hm, p_w2pad, m1b2, p_E,
                                               NODES, 256, 384);
    pool_kernel<<<GB, 256>>>(p_E, p_pool);
    head_kernel<<<GB, 128>>>(p_pool, m2w1, m2b1, m2w2, m2b2, (float*)d_out);
}

// round 5
// speedup vs baseline: 1.1079x; 1.1079x over previous
#include <cuda_runtime.h>

// ---------------------------------------------------------------------------
// DynEdge: 4x DynamicEdgeConv (kNN in feature space, K=8) + MLP head.
// R4: SGEMM microkernel converted to packed fp32x2 (fma.rn.f32x2, FFMA2) —
// Blackwell double-rate fp32. Bit-identical math, 2x FMA-pipe throughput.
// ---------------------------------------------------------------------------

#define GB    64
#define GN    512
#define NODES 32768          // GB*GN
#define KNB   8

typedef unsigned long long ull;

static inline int cdiv(int a, int b) { return (a + b - 1) / b; }

__device__ __forceinline__ float lrelu(float v) { return v >= 0.0f ? v : 0.01f * v; }

__device__ __forceinline__ void ffma2(ull& acc, ull a, ull b) {
    asm("fma.rn.f32x2 %0, %1, %2, %0;" : "+l"(acc) : "l"(a), "l"(b));
}
__device__ __forceinline__ ull pack2(float x) {
    ull r;
    asm("mov.b64 %0, {%1, %1};" : "=l"(r) : "f"(x));
    return r;
}
__device__ __forceinline__ float2 unpack2(ull v) {
    float2 r;
    asm("mov.b64 {%0, %1}, %2;" : "=f"(r.x), "=f"(r.y) : "l"(v));
    return r;
}

// ------------------------------- scratch -----------------------------------
__device__ float g_x0p  [NODES * 8];                 // x padded [32768,8]
__device__ float g_featv[4 * NODES * 256];           // x1..x4
__device__ float g_gramv[(size_t)GB * GN * GN];      // per-graph Gram
__device__ float g_x2v  [NODES];
__device__ int   g_knnv [NODES * KNB];               // global neighbor ids
__device__ float g_wcombv[256 * 768];                // [(Wa-Wb) | Wb | 0] padded
__device__ float g_cbv  [(size_t)NODES * 768];       // [c | b] per node
__device__ float g_H1v  [(size_t)NODES * KNB * 336]; // edge hidden
__device__ float g_Ev   [(size_t)NODES * KNB * 256]; // edge out (also reused for m1 h)
__device__ float g_hcatv[(size_t)NODES * 1032];
__device__ float g_hmv  [(size_t)NODES * 384];
__device__ float g_w1padv[1032 * 384];
__device__ float g_b1padv[384];
__device__ float g_w2padv[384 * 256];
__device__ float g_poolv[GB * 256];

// ------------------------------ SGEMM (NN) ---------------------------------
// C[M,N] = A[M,K] @ B[K,N]. Requires M%128==0, N%128==0, K%8==0, 16B-aligned
// rows. 128x128 block tile, 8x8 per-thread microtile held as 8x4 f32x2 pairs,
// double-buffered smem. EPI==1: C = lrelu(C + bias[col]).
template <int EPI>
__global__ __launch_bounds__(256)
void sgemm_nn(const float* __restrict__ A, const float* __restrict__ B,
              const float* __restrict__ bias, float* __restrict__ C,
              int M, int N, int K)
{
    __shared__ float As[2][8][128];
    __shared__ float Bs[2][8][128];
    const int tid  = threadIdx.x;
    const int m0   = blockIdx.x * 128;
    const int n0   = blockIdx.y * 128;
    const int tx   = tid & 15;
    const int ty   = tid >> 4;
    const int arow = tid >> 1;
    const int acol = (tid & 1) << 2;
    const int brow = tid >> 5;
    const int bcol = (tid & 31) << 2;

    const float* Ap = A + (size_t)(m0 + arow) * K + acol;
    const float* Bp = B + (size_t)brow * N + (n0 + bcol);

    float4 av = *(const float4*)Ap;
    float4 bv = *(const float4*)Bp;
    As[0][acol + 0][arow] = av.x;
    As[0][acol + 1][arow] = av.y;
    As[0][acol + 2][arow] = av.z;
    As[0][acol + 3][arow] = av.w;
    *(float4*)&Bs[0][brow][bcol] = bv;
    __syncthreads();

    ull acc[8][4];
#pragma unroll
    for (int i = 0; i < 8; i++)
#pragma unroll
        for (int j = 0; j < 4; j++) acc[i][j] = 0ull;

    const int nk = K >> 3;
    for (int kc = 0; kc < nk; kc++) {
        const int cur = kc & 1;
        const bool has_next = (kc + 1 < nk);
        if (has_next) {
            av = *(const float4*)(Ap + (kc + 1) * 8);
            bv = *(const float4*)(Bp + (size_t)(kc + 1) * 8 * N);
        }
#pragma unroll
        for (int k = 0; k < 8; k++) {
            float ar[8];
            ull bp[4];
            *(float4*)&ar[0] = *(const float4*)&As[cur][k][ty * 4];
            *(float4*)&ar[4] = *(const float4*)&As[cur][k][64 + ty * 4];
            {
                ulonglong2 t0 = *(const ulonglong2*)&Bs[cur][k][tx * 4];
                ulonglong2 t1 = *(const ulonglong2*)&Bs[cur][k][64 + tx * 4];
                bp[0] = t0.x; bp[1] = t0.y; bp[2] = t1.x; bp[3] = t1.y;
            }
#pragma unroll
            for (int i = 0; i < 8; i++) {
                const ull ai = pack2(ar[i]);
                ffma2(acc[i][0], ai, bp[0]);
                ffma2(acc[i][1], ai, bp[1]);
                ffma2(acc[i][2], ai, bp[2]);
                ffma2(acc[i][3], ai, bp[3]);
            }
        }
        if (has_next) {
            const int nxt = cur ^ 1;
            As[nxt][acol + 0][arow] = av.x;
            As[nxt][acol + 1][arow] = av.y;
            As[nxt][acol + 2][arow] = av.z;
            As[nxt][acol + 3][arow] = av.w;
            *(float4*)&Bs[nxt][brow][bcol] = bv;
        }
        __syncthreads();
    }

#pragma unroll
    for (int i = 0; i < 8; i++) {
        const int r = m0 + ((i < 4) ? (ty * 4 + i) : (64 + ty * 4 + i - 4));
#pragma unroll
        for (int h = 0; h < 2; h++) {
            const int c = n0 + h * 64 + tx * 4;
            float2 p0 = unpack2(acc[i][h * 2 + 0]);
            float2 p1 = unpack2(acc[i][h * 2 + 1]);
            float4 v;
            v.x = p0.x; v.y = p0.y; v.z = p1.x; v.w = p1.y;
            if (EPI == 1) {
                v.x = lrelu(v.x + bias[c + 0]);
                v.y = lrelu(v.y + bias[c + 1]);
                v.z = lrelu(v.z + bias[c + 2]);
                v.w = lrelu(v.w + bias[c + 3]);
            }
            *(float4*)&C[(size_t)r * N + c] = v;
        }
    }
}

// ----------------------- batched Gram: G = X @ X^T -------------------------
// grid (4, 4, 64): 128x128 tile of one graph's 512x512 Gram. ldx = K (8 or 256).
__global__ __launch_bounds__(256)
void gram_nt(const float* __restrict__ X, int ldx, int K, float* __restrict__ G)
{
    const int b = blockIdx.z;
    const float* A = X + (size_t)b * GN * ldx;
    float* C = G + (size_t)b * GN * GN;
    __shared__ float As[2][8][128];
    __shared__ float Bs[2][8][128];
    const int tid  = threadIdx.x;
    const int m0   = blockIdx.x * 128;
    const int n0   = blockIdx.y * 128;
    const int tx   = tid & 15;
    const int ty   = tid >> 4;
    const int arow = tid >> 1;
    const int acol = (tid & 1) << 2;

    const float* Ap = A + (size_t)(m0 + arow) * ldx + acol;
    const float* Bp = A + (size_t)(n0 + arow) * ldx + acol;

    float4 av = *(const float4*)Ap;
    float4 bv = *(const float4*)Bp;
    As[0][acol + 0][arow] = av.x; As[0][acol + 1][arow] = av.y;
    As[0][acol + 2][arow] = av.z; As[0][acol + 3][arow] = av.w;
    Bs[0][acol + 0][arow] = bv.x; Bs[0][acol + 1][arow] = bv.y;
    Bs[0][acol + 2][arow] = bv.z; Bs[0][acol + 3][arow] = bv.w;
    __syncthreads();

    ull acc[8][4];
#pragma unroll
    for (int i = 0; i < 8; i++)
#pragma unroll
        for (int j = 0; j < 4; j++) acc[i][j] = 0ull;

    const int nk = K >> 3;
    for (int kc = 0; kc < nk; kc++) {
        const int cur = kc & 1;
        const bool has_next = (kc + 1 < nk);
        if (has_next) {
            av = *(const float4*)(Ap + (kc + 1) * 8);
            bv = *(const float4*)(Bp + (kc + 1) * 8);
        }
#pragma unroll
        for (int k = 0; k < 8; k++) {
            float ar[8];
            ull bp[4];
            *(float4*)&ar[0] = *(const float4*)&As[cur][k][ty * 4];
            *(float4*)&ar[4] = *(const float4*)&As[cur][k][64 + ty * 4];
            {
                ulonglong2 t0 = *(const ulonglong2*)&Bs[cur][k][tx * 4];
                ulonglong2 t1 = *(const ulonglong2*)&Bs[cur][k][64 + tx * 4];
                bp[0] = t0.x; bp[1] = t0.y; bp[2] = t1.x; bp[3] = t1.y;
            }
#pragma unroll
            for (int i = 0; i < 8; i++) {
                const ull ai = pack2(ar[i]);
                ffma2(acc[i][0], ai, bp[0]);
                ffma2(acc[i][1], ai, bp[1]);
                ffma2(acc[i][2], ai, bp[2]);
                ffma2(acc[i][3], ai, bp[3]);
            }
        }
        if (has_next) {
            const int nxt = cur ^ 1;
            As[nxt][acol + 0][arow] = av.x; As[nxt][acol + 1][arow] = av.y;
            As[nxt][acol + 2][arow] = av.z; As[nxt][acol + 3][arow] = av.w;
            Bs[nxt][acol + 0][arow] = bv.x; Bs[nxt][acol + 1][arow] = bv.y;
            Bs[nxt][acol + 2][arow] = bv.z; Bs[nxt][acol + 3][arow] = bv.w;
        }
        __syncthreads();
    }

#pragma unroll
    for (int i = 0; i < 8; i++) {
        const int r = m0 + ((i < 4) ? (ty * 4 + i) : (64 + ty * 4 + i - 4));
#pragma unroll
        for (int h = 0; h < 2; h++) {
            const int c = n0 + h * 64 + tx * 4;
            float2 p0 = unpack2(acc[i][h * 2 + 0]);
            float2 p1 = unpack2(acc[i][h * 2 + 1]);
            float4 v;
            v.x = p0.x; v.y = p0.y; v.z = p1.x; v.w = p1.y;
            *(float4*)&C[(size_t)r * GN + c] = v;
        }
    }
}

// ------------------------------- helpers -----------------------------------
__global__ void x2_kernel(const float* __restrict__ X, int Fp, float* __restrict__ x2)
{
    int i = blockIdx.x * blockDim.x + threadIdx.x;
    if (i >= NODES) return;
    const float* p = X + (size_t)i * Fp;
    float s = 0.f;
    for (int f = 0; f < Fp; f += 4) {
        float4 v = *(const float4*)(p + f);
        s += v.x * v.x + v.y * v.y + v.z * v.z + v.w * v.w;
    }
    x2[i] = s;
}

// top-8 smallest distances, stable on ties (lower index wins) to match lax.top_k
__global__ __launch_bounds__(512)
void knn_kernel(const float* __restrict__ G, const float* __restrict__ x2,
                int* __restrict__ knn)
{
    const int b = blockIdx.x;
    const int i = threadIdx.x;
    __shared__ float sx2[GN];
    sx2[i] = x2[b * GN + i];
    __syncthreads();
    const float x2i = sx2[i];
    const float4* row = (const float4*)(G + ((size_t)b * GN + i) * GN);

    float bd[8]; int bi[8];
#pragma unroll
    for (int k = 0; k < 8; k++) { bd[k] = 3.4e38f; bi[k] = 0; }

    for (int q = 0; q < GN / 4; q++) {
        float4 g4 = row[q];
        const int j = q * 4;
        float dv0 = x2i + sx2[j + 0] - 2.0f * g4.x;
        float dv1 = x2i + sx2[j + 1] - 2.0f * g4.y;
        float dv2 = x2i + sx2[j + 2] - 2.0f * g4.z;
        float dv3 = x2i + sx2[j + 3] - 2.0f * g4.w;
        float dv[4] = {dv0, dv1, dv2, dv3};
#pragma unroll
        for (int u = 0; u < 4; u++) {
            float d = dv[u];
            if (d < bd[7]) {
                bd[7] = d; bi[7] = j + u;
#pragma unroll
                for (int s = 7; s > 0; s--) {
                    if (bd[s] < bd[s - 1]) {
                        float td = bd[s]; bd[s] = bd[s - 1]; bd[s - 1] = td;
                        int   ti = bi[s]; bi[s] = bi[s - 1]; bi[s - 1] = ti;
                    } else break;
                }
            }
        }
    }
#pragma unroll
    for (int k = 0; k < 8; k++)
        knn[((size_t)b * GN + i) * KNB + k] = b * GN + bi[k];
}

// wcomb[f, 0:336]   = W1[f] - W1[F+f]   (multiplies x_i)
// wcomb[f, 336:672] = W1[F+f]           (multiplies x_j)
// wcomb[f, 672:768] = 0 ; rows f>=F zero.
__global__ void build_wcomb(const float* __restrict__ W1, int F, int Fp,
                            float* __restrict__ out)
{
    int idx = blockIdx.x * blockDim.x + threadIdx.x;
    if (idx >= Fp * 768) return;
    int f = idx / 768, t = idx % 768;
    float v = 0.f;
    if (f < F) {
        if (t < 336)      v = W1[f * 336 + t] - W1[(F + f) * 336 + t];
        else if (t < 672) v = W1[(F + f) * 336 + (t - 336)];
    }
    out[idx] = v;
}

__global__ void pad_w(const float* __restrict__ src, int R, int Cs,
                      float* __restrict__ dst, int Rp, int Cp)
{
    int idx = blockIdx.x * blockDim.x + threadIdx.x;
    if (idx >= Rp * Cp) return;
    int r = idx / Cp, c = idx % Cp;
    dst[idx] = (r < R && c < Cs) ? src[r * Cs + c] : 0.f;
}

// H1[edge, t] = lrelu(c_i[t] + b_j[t] + bias1[t])
__global__ void edge_build(const float* __restrict__ cb, const int* __restrict__ knn,
                           const float* __restrict__ b1, float* __restrict__ H1)
{
    const int node = blockIdx.x;
    const int tid = threadIdx.x;
    __shared__ int js[KNB];
    if (tid < KNB) js[tid] = knn[(size_t)node * KNB + tid];
    __syncthreads();
    const float* ci = cb + (size_t)node * 768;
#pragma unroll
    for (int k = 0; k < KNB; k++) {
        const float* bj = cb + (size_t)js[k] * 768 + 336;
        float* out = H1 + ((size_t)node * KNB + k) * 336;
        for (int t = tid; t < 336; t += blockDim.x)
            out[t] = lrelu(ci[t] + bj[t] + b1[t]);
    }
}

// out[node,c] = lrelu(max_k E[node*8+k, c] + b2[c])   (lrelu monotone)
__global__ void edge_reduce(const float* __restrict__ E, const float* __restrict__ b2,
                            float* __restrict__ out)
{
    const int node = blockIdx.x;
    const int c = threadIdx.x;
    float m = -3.4e38f;
#pragma unroll
    for (int k = 0; k < KNB; k++)
        m = fmaxf(m, E[((size_t)node * KNB + k) * 256 + c]);
    out[(size_t)node * 256 + c] = lrelu(m + b2[c]);
}

__global__ void concat_kernel(const float* __restrict__ x0,
                              const float* __restrict__ f1, const float* __restrict__ f2,
                              const float* __restrict__ f3, const float* __restrict__ f4,
                              float* __restrict__ out)
{
    const int row = blockIdx.x;
    for (int col = threadIdx.x; col < 1032; col += blockDim.x) {
        float v;
        if (col < 6)         v = x0[row * 6 + col];
        else if (col < 262)  v = f1[(size_t)row * 256 + col - 6];
        else if (col < 518)  v = f2[(size_t)row * 256 + col - 262];
        else if (col < 774)  v = f3[(size_t)row * 256 + col - 518];
        else if (col < 1030) v = f4[(size_t)row * 256 + col - 774];
        else                 v = 0.f;
        out[(size_t)row * 1032 + col] = v;
    }
}

__global__ void pool_kernel(const float* __restrict__ h, float* __restrict__ g)
{
    const int b = blockIdx.x, c = threadIdx.x;
    float s = 0.f;
    for (int n = 0; n < GN; n++)
        s += h[((size_t)b * GN + n) * 256 + c];
    g[b * 256 + c] = s * (1.0f / GN);
}

__global__ void head_kernel(const float* __restrict__ gpool,
                            const float* __restrict__ w1, const float* __restrict__ b1,
                            const float* __restrict__ w2, const float* __restrict__ b2,
                            float* __restrict__ out)
{
    const int b = blockIdx.x, tid = threadIdx.x;  // 128 threads
    __shared__ float g[256];
    __shared__ float mid[128];
    g[tid] = gpool[b * 256 + tid];
    g[tid + 128] = gpool[b * 256 + tid + 128];
    __syncthreads();
    float s = b1[tid];
    for (int f = 0; f < 256; f++)
        s = fmaf(g[f], w1[f * 128 + tid], s);
    mid[tid] = lrelu(s);
    __syncthreads();
    if (tid < 3) {
        float s2 = b2[tid];
        for (int f = 0; f < 128; f++)
            s2 = fmaf(mid[f], w2[f * 3 + tid], s2);
        out[b * 3 + tid] = s2;
    }
}

// ------------------------------- launcher ----------------------------------
extern "C" void kernel_launch(void* const* d_in, const int* in_sizes, int n_in,
                              void* d_out, int out_size)
{
    (void)in_sizes; (void)n_in; (void)out_size;
    const float* x = (const float*)d_in[0];
    const float* cw1[4] = {(const float*)d_in[3],  (const float*)d_in[7],
                           (const float*)d_in[11], (const float*)d_in[15]};
    const float* cb1[4] = {(const float*)d_in[4],  (const float*)d_in[8],
                           (const float*)d_in[12], (const float*)d_in[16]};
    const float* cw2[4] = {(const float*)d_in[5],  (const float*)d_in[9],
                           (const float*)d_in[13], (const float*)d_in[17]};
    const float* cb2[4] = {(const float*)d_in[6],  (const float*)d_in[10],
                           (const float*)d_in[14], (const float*)d_in[18]};
    const float* m1w1 = (const float*)d_in[19];
    const float* m1b1 = (const float*)d_in[20];
    const float* m1w2 = (const float*)d_in[21];
    const float* m1b2 = (const float*)d_in[22];
    const float* m2w1 = (const float*)d_in[23];
    const float* m2b1 = (const float*)d_in[24];
    const float* m2w2 = (const float*)d_in[25];
    const float* m2b2 = (const float*)d_in[26];

    float *p_x0p, *p_feat, *p_gram, *p_x2, *p_wcomb, *p_cb, *p_H1, *p_E;
    float *p_hcat, *p_hm, *p_w1pad, *p_b1pad, *p_w2pad, *p_pool;
    int* p_knn;
    cudaGetSymbolAddress((void**)&p_x0p,   g_x0p);
    cudaGetSymbolAddress((void**)&p_feat,  g_featv);
    cudaGetSymbolAddress((void**)&p_gram,  g_gramv);
    cudaGetSymbolAddress((void**)&p_x2,    g_x2v);
    cudaGetSymbolAddress((void**)&p_knn,   g_knnv);
    cudaGetSymbolAddress((void**)&p_wcomb, g_wcombv);
    cudaGetSymbolAddress((void**)&p_cb,    g_cbv);
    cudaGetSymbolAddress((void**)&p_H1,    g_H1v);
    cudaGetSymbolAddress((void**)&p_E,     g_Ev);
    cudaGetSymbolAddress((void**)&p_hcat,  g_hcatv);
    cudaGetSymbolAddress((void**)&p_hm,    g_hmv);
    cudaGetSymbolAddress((void**)&p_w1pad, g_w1padv);
    cudaGetSymbolAddress((void**)&p_b1pad, g_b1padv);
    cudaGetSymbolAddress((void**)&p_w2pad, g_w2padv);
    cudaGetSymbolAddress((void**)&p_pool,  g_poolv);

    // ---- prep: pad inputs/weights for the GEMM tiling constraints ----
    pad_w<<<cdiv(NODES * 8, 256), 256>>>(x, NODES, 6, p_x0p, NODES, 8);
    pad_w<<<cdiv(1032 * 384, 256), 256>>>(m1w1, 1030, 336, p_w1pad, 1032, 384);
    pad_w<<<cdiv(384, 256), 256>>>(m1b1, 1, 336, p_b1pad, 1, 384);
    pad_w<<<cdiv(384 * 256, 256), 256>>>(m1w2, 336, 256, p_w2pad, 384, 256);

    // ---- 4 DynamicEdgeConv layers ----
    for (int l = 0; l < 4; l++) {
        const float* in = (l == 0) ? p_x0p : (p_feat + (size_t)(l - 1) * NODES * 256);
        const int Fp = (l == 0) ? 8 : 256;
        const int F  = (l == 0) ? 6 : 256;

        x2_kernel<<<cdiv(NODES, 256), 256>>>(in, Fp, p_x2);
        gram_nt<<<dim3(4, 4, GB), 256>>>(in, Fp, Fp, p_gram);
        knn_kernel<<<GB, GN>>>(p_gram, p_x2, p_knn);

        build_wcomb<<<cdiv(Fp * 768, 256), 256>>>(cw1[l], F, Fp, p_wcomb);
        sgemm_nn<0><<<dim3(NODES / 128, 6), 256>>>(in, p_wcomb, nullptr, p_cb,
                                                   NODES, 768, Fp);
        edge_build<<<NODES, 256>>>(p_cb, p_knn, cb1[l], p_H1);
        sgemm_nn<0><<<dim3(NODES * KNB / 128, 2), 256>>>(p_H1, cw2[l], nullptr, p_E,
                                                         NODES * KNB, 256, 336);
        edge_reduce<<<NODES, 256>>>(p_E, cb2[l], p_feat + (size_t)l * NODES * 256);
    }

    // ---- head ----
    concat_kernel<<<NODES, 256>>>(x,
                                  p_feat + (size_t)0 * NODES * 256,
                                  p_feat + (size_t)1 * NODES * 256,
                                  p_feat + (size_t)2 * NODES * 256,
                                  p_feat + (size_t)3 * NODES * 256,
                                  p_hcat);
    sgemm_nn<1><<<dim3(NODES / 128, 3), 256>>>(p_hcat, p_w1pad, p_b1pad, p_hm,
                                               NODES, 384, 1032);
    sgemm_nn<1><<<dim3(NODES / 128, 2), 256>>>(p_hm, p_w2pad, m1b2, p_E,
                                               NODES, 256, 384);
    pool_kernel<<<GB, 256>>>(p_E, p_pool);
    head_kernel<<<GB, 128>>>(p_pool, m2w1, m2b1, m2w2, m2b2, (float*)d_out);
}